// round 9
// baseline (speedup 1.0000x reference)
#include <cuda_runtime.h>
#include <cuda_bf16.h>
#include <stdint.h>

// ---------------------------------------------------------------------------
// LlamaAttention: S=2048, HID=4096, NH=32, NKV=8, D=128
// All matmuls via warp mma.sync bf16x3 (tcgen05 unavailable: PTX target 103).
// RoPE fused into QKV-GEMM epilogue. Flash: delayed-PV pipeline, Q-hi in regs,
// K+V double-buffered, 160.8KB SMEM, 1 CTA/SM.
// ---------------------------------------------------------------------------

#define S_LEN 2048
#define HID   4096
#define NH    32
#define NKV   8
#define HD    128
#define KVDIM (NKV * HD)   // 1024

// fp32 scratch (V only)
__device__ float g_v[S_LEN * KVDIM];

// bf16 split scratch
__device__ __nv_bfloat16 g_hid_hi[S_LEN * HID];
__device__ __nv_bfloat16 g_hid_lo[S_LEN * HID];
__device__ __nv_bfloat16 g_wq_hi[HID * HID];
__device__ __nv_bfloat16 g_wq_lo[HID * HID];
__device__ __nv_bfloat16 g_wk_hi[KVDIM * HID];
__device__ __nv_bfloat16 g_wk_lo[KVDIM * HID];
__device__ __nv_bfloat16 g_wv_hi[KVDIM * HID];
__device__ __nv_bfloat16 g_wv_lo[KVDIM * HID];
__device__ __nv_bfloat16 g_wo_hi[HID * HID];
__device__ __nv_bfloat16 g_wo_lo[HID * HID];
__device__ __nv_bfloat16 g_attn_hi[S_LEN * HID];
__device__ __nv_bfloat16 g_attn_lo[S_LEN * HID];
__device__ __nv_bfloat16 g_qr_hi[S_LEN * HID];
__device__ __nv_bfloat16 g_qr_lo[S_LEN * HID];
__device__ __nv_bfloat16 g_kr_hi[S_LEN * KVDIM];
__device__ __nv_bfloat16 g_kr_lo[S_LEN * KVDIM];
__device__ __nv_bfloat16 g_vt_hi[KVDIM * S_LEN];
__device__ __nv_bfloat16 g_vt_lo[KVDIM * S_LEN];

__device__ __forceinline__ uint32_t pack_hl(float f0, float f1, uint32_t& lo) {
    __nv_bfloat162 h = __floats2bfloat162_rn(f0, f1);
    float r0 = f0 - __bfloat162float(h.x);
    float r1 = f1 - __bfloat162float(h.y);
    __nv_bfloat162 l = __floats2bfloat162_rn(r0, r1);
    lo = *(uint32_t*)&l;
    return *(uint32_t*)&h;
}

// ---------------------------------------------------------------------------
// fused split
// ---------------------------------------------------------------------------
#define N_HID (S_LEN * HID)
#define N_WQ  (HID * HID)
#define N_WKV (KVDIM * HID)
#define SEG0  N_HID
#define SEG1  (SEG0 + N_WQ)
#define SEG2  (SEG1 + N_WKV)
#define SEG3  (SEG2 + N_WKV)
#define SEG4  (SEG3 + N_WQ)
#define SPLIT_GRID (SEG4 / (8 * 256))

__device__ __forceinline__ void split8(const float* src, __nv_bfloat16* hi,
                                       __nv_bfloat16* lo, int off) {
    float4 f[2];
    f[0] = *(const float4*)(src + off);
    f[1] = *(const float4*)(src + off + 4);
#pragma unroll
    for (int j = 0; j < 2; j++) {
        __nv_bfloat16 h0 = __float2bfloat16(f[j].x);
        __nv_bfloat16 h1 = __float2bfloat16(f[j].y);
        __nv_bfloat16 h2 = __float2bfloat16(f[j].z);
        __nv_bfloat16 h3 = __float2bfloat16(f[j].w);
        __nv_bfloat16 l0 = __float2bfloat16(f[j].x - __bfloat162float(h0));
        __nv_bfloat16 l1 = __float2bfloat16(f[j].y - __bfloat162float(h1));
        __nv_bfloat16 l2 = __float2bfloat16(f[j].z - __bfloat162float(h2));
        __nv_bfloat16 l3 = __float2bfloat16(f[j].w - __bfloat162float(h3));
        ushort4 hv, lv;
        hv.x = *(unsigned short*)&h0; hv.y = *(unsigned short*)&h1;
        hv.z = *(unsigned short*)&h2; hv.w = *(unsigned short*)&h3;
        lv.x = *(unsigned short*)&l0; lv.y = *(unsigned short*)&l1;
        lv.z = *(unsigned short*)&l2; lv.w = *(unsigned short*)&l3;
        *(ushort4*)(hi + off + j * 4) = hv;
        *(ushort4*)(lo + off + j * 4) = lv;
    }
}

__global__ void split_all(const float* __restrict__ hidden,
                          const float* __restrict__ wq,
                          const float* __restrict__ wk,
                          const float* __restrict__ wv,
                          const float* __restrict__ wo) {
    int g = (blockIdx.x * blockDim.x + threadIdx.x) * 8;
    if (g < SEG0)      split8(hidden, g_hid_hi, g_hid_lo, g);
    else if (g < SEG1) split8(wq, g_wq_hi, g_wq_lo, g - SEG0);
    else if (g < SEG2) split8(wk, g_wk_hi, g_wk_lo, g - SEG1);
    else if (g < SEG3) split8(wv, g_wv_hi, g_wv_lo, g - SEG2);
    else               split8(wo, g_wo_hi, g_wo_lo, g - SEG3);
}

// ---------------------------------------------------------------------------
// warp-MMA primitives
// ---------------------------------------------------------------------------
__device__ __forceinline__ void ldsm_x4(uint32_t addr, uint32_t& r0, uint32_t& r1,
                                        uint32_t& r2, uint32_t& r3) {
    asm volatile("ldmatrix.sync.aligned.m8n8.x4.shared.b16 {%0,%1,%2,%3}, [%4];"
                 : "=r"(r0), "=r"(r1), "=r"(r2), "=r"(r3) : "r"(addr));
}

__device__ __forceinline__ void mma_bf16(float* c, const uint32_t* a, const uint32_t* b) {
    asm volatile(
        "mma.sync.aligned.m16n8k16.row.col.f32.bf16.bf16.f32 "
        "{%0,%1,%2,%3},{%4,%5,%6,%7},{%8,%9},{%0,%1,%2,%3};"
        : "+f"(c[0]), "+f"(c[1]), "+f"(c[2]), "+f"(c[3])
        : "r"(a[0]), "r"(a[1]), "r"(a[2]), "r"(a[3]), "r"(b[0]), "r"(b[1]));
}

// ---------------------------------------------------------------------------
// bf16x3 GEMM body: block 256x128, warp 64x64, BK=64, 256 thr, 2-stage.
// ---------------------------------------------------------------------------
#define GBK  64
#define LDT  144
#define A_T  (256 * LDT)
#define B_T  (128 * LDT)
#define STG  (2 * A_T + 2 * B_T)
#define GEMM_SMEM (2 * STG)

__device__ __forceinline__ void gemm_body256(
    const __nv_bfloat16* __restrict__ Ah, const __nv_bfloat16* __restrict__ Al,
    const __nv_bfloat16* __restrict__ Bh, const __nv_bfloat16* __restrict__ Bl,
    float* __restrict__ Cf, __nv_bfloat16* __restrict__ Chi,
    __nv_bfloat16* __restrict__ Clo,
    const float* __restrict__ cosb, const float* __restrict__ sinb,
    int mode, int N, int K, int bm, int bn, char* smem) {
    const int tid = threadIdx.x;
    const int lane = tid & 31;
    const int warp = tid >> 5;
    const int wr = warp >> 1;
    const int wc = warp & 1;
    uint32_t sbase = (uint32_t)__cvta_generic_to_shared(smem);

    float acc[4][8][4];
#pragma unroll
    for (int mi = 0; mi < 4; mi++)
#pragma unroll
        for (int ni = 0; ni < 8; ni++)
#pragma unroll
            for (int t = 0; t < 4; t++) acc[mi][ni][t] = 0.f;

    auto load_stage = [&](int s, int it) {
        const int kbase = it * GBK;
        uint32_t dst0 = sbase + s * STG;
#pragma unroll
        for (int i = 0; i < 24; i++) {
            int c = tid + i * 256;
            const __nv_bfloat16* gsrc;
            uint32_t daddr;
            if (c < 4096) {
                int mat = c >> 11;
                int idx = c & 2047;
                int row = idx >> 3;
                int ch = idx & 7;
                gsrc = (mat ? Al : Ah) + (size_t)(bm + row) * K + kbase + ch * 8;
                daddr = dst0 + mat * A_T + row * LDT + ch * 16;
            } else {
                int cb = c - 4096;
                int mat = cb >> 10;
                int idx = cb & 1023;
                int row = idx >> 3;
                int ch = idx & 7;
                gsrc = (mat ? Bl : Bh) + (size_t)(bn + row) * K + kbase + ch * 8;
                daddr = dst0 + 2 * A_T + mat * B_T + row * LDT + ch * 16;
            }
            asm volatile("cp.async.cg.shared.global [%0], [%1], 16;"
                         :: "r"(daddr), "l"(gsrc));
        }
        asm volatile("cp.async.commit_group;");
    };

    const int NIT = K / GBK;
    load_stage(0, 0);
    load_stage(1, 1);

    const int brow = (lane & 7) + ((lane >> 4) << 3);
    const int bch = (lane >> 3) & 1;

    for (int it = 0; it < NIT; it++) {
        asm volatile("cp.async.wait_group 1;");
        __syncthreads();

        uint32_t sa = sbase + (it & 1) * STG;
#pragma unroll
        for (int ks = 0; ks < 4; ks++) {
            uint32_t ah[4][4], al[4][4];
#pragma unroll
            for (int mi = 0; mi < 4; mi++) {
                uint32_t off = (uint32_t)((wr * 64 + mi * 16 + (lane & 15)) * LDT +
                                          ks * 32 + ((lane >> 4) & 1) * 16);
                ldsm_x4(sa + off, ah[mi][0], ah[mi][1], ah[mi][2], ah[mi][3]);
                ldsm_x4(sa + A_T + off, al[mi][0], al[mi][1], al[mi][2], al[mi][3]);
            }
#pragma unroll
            for (int half = 0; half < 2; half++) {
                uint32_t bh[4][2], bl[4][2];
#pragma unroll
                for (int np = 0; np < 2; np++) {
                    uint32_t off = (uint32_t)((wc * 64 + half * 32 + np * 16 + brow) * LDT +
                                              ks * 32 + bch * 16);
                    uint32_t r0, r1, r2, r3;
                    ldsm_x4(sa + 2 * A_T + off, r0, r1, r2, r3);
                    bh[np * 2][0] = r0; bh[np * 2][1] = r1;
                    bh[np * 2 + 1][0] = r2; bh[np * 2 + 1][1] = r3;
                    ldsm_x4(sa + 2 * A_T + B_T + off, r0, r1, r2, r3);
                    bl[np * 2][0] = r0; bl[np * 2][1] = r1;
                    bl[np * 2 + 1][0] = r2; bl[np * 2 + 1][1] = r3;
                }
#pragma unroll
                for (int mi = 0; mi < 4; mi++)
#pragma unroll
                    for (int nf = 0; nf < 4; nf++) {
                        float* a = acc[mi][half * 4 + nf];
                        mma_bf16(a, ah[mi], bh[nf]);
                        mma_bf16(a, ah[mi], bl[nf]);
                        mma_bf16(a, al[mi], bh[nf]);
                    }
            }
        }
        __syncthreads();
        if (it + 2 < NIT) load_stage(it & 1, it + 2);
        else              asm volatile("cp.async.commit_group;");
    }

    if (mode == 0) {
#pragma unroll
        for (int mi = 0; mi < 4; mi++) {
            const int r0 = bm + wr * 64 + mi * 16 + (lane >> 2);
#pragma unroll
            for (int ni = 0; ni < 8; ni++) {
                const int col = bn + wc * 64 + ni * 8 + (lane & 3) * 2;
                *(float2*)&Cf[(size_t)r0 * N + col] = make_float2(acc[mi][ni][0], acc[mi][ni][1]);
                *(float2*)&Cf[(size_t)(r0 + 8) * N + col] = make_float2(acc[mi][ni][2], acc[mi][ni][3]);
            }
        }
    } else {
#pragma unroll
        for (int mi = 0; mi < 4; mi++) {
            const int r0 = bm + wr * 64 + mi * 16 + (lane >> 2);
            const int r1 = r0 + 8;
#pragma unroll
            for (int ni = 0; ni < 8; ni++) {
                const int col = bn + wc * 64 + ni * 8 + (lane & 3) * 2;
                const int i = (col & 127) >> 1;
                float c0 = cosb[r0 * 64 + i];
                float s0 = sinb[r0 * 64 + i];
                float c1 = cosb[r1 * 64 + i];
                float s1 = sinb[r1 * 64 + i];
                float a0 = acc[mi][ni][0], b0 = acc[mi][ni][1];
                float a1 = acc[mi][ni][2], b1 = acc[mi][ni][3];
                float x0 = a0 * c0 - b0 * s0, y0 = a0 * s0 + b0 * c0;
                float x1 = a1 * c1 - b1 * s1, y1 = a1 * s1 + b1 * c1;
                uint32_t lo32, hi32;
                hi32 = pack_hl(x0, y0, lo32);
                *(uint32_t*)&Chi[(size_t)r0 * N + col] = hi32;
                *(uint32_t*)&Clo[(size_t)r0 * N + col] = lo32;
                hi32 = pack_hl(x1, y1, lo32);
                *(uint32_t*)&Chi[(size_t)r1 * N + col] = hi32;
                *(uint32_t*)&Clo[(size_t)r1 * N + col] = lo32;
            }
        }
    }
}

__global__ __launch_bounds__(256, 1) void gemm_qkv(const float* __restrict__ cosb,
                                                   const float* __restrict__ sinb) {
    extern __shared__ char smem[];
    const int bng = blockIdx.y * 128;
    const int bm = blockIdx.x * 256;
    if (bng < HID) {
        gemm_body256(g_hid_hi, g_hid_lo, g_wq_hi, g_wq_lo, nullptr,
                     g_qr_hi, g_qr_lo, cosb, sinb, 1, HID, HID, bm, bng, smem);
    } else if (bng < HID + KVDIM) {
        gemm_body256(g_hid_hi, g_hid_lo, g_wk_hi, g_wk_lo, nullptr,
                     g_kr_hi, g_kr_lo, cosb, sinb, 1, KVDIM, HID, bm, bng - HID, smem);
    } else {
        gemm_body256(g_hid_hi, g_hid_lo, g_wv_hi, g_wv_lo, g_v,
                     nullptr, nullptr, nullptr, nullptr, 0, KVDIM, HID,
                     bm, bng - HID - KVDIM, smem);
    }
}

__global__ __launch_bounds__(256, 1) void gemm_o(float* __restrict__ out) {
    extern __shared__ char smem[];
    gemm_body256(g_attn_hi, g_attn_lo, g_wo_hi, g_wo_lo, out, nullptr, nullptr,
                 nullptr, nullptr, 0, HID, HID,
                 blockIdx.x * 256, blockIdx.y * 128, smem);
}

// ---------------------------------------------------------------------------
// transpose + split
// ---------------------------------------------------------------------------
__global__ void transpose_split(const float* __restrict__ v,
                                __nv_bfloat16* __restrict__ th,
                                __nv_bfloat16* __restrict__ tl) {
    __shared__ float tile[32][33];
    const int bs = blockIdx.x * 32;
    const int bd = blockIdx.y * 32;
    const int tx = threadIdx.x;
    const int ty = threadIdx.y;
#pragma unroll
    for (int i = 0; i < 4; i++) {
        int sy = ty * 4 + i;
        tile[sy][tx] = v[(size_t)(bs + sy) * KVDIM + bd + tx];
    }
    __syncthreads();
#pragma unroll
    for (int i = 0; i < 4; i++) {
        int dy = ty * 4 + i;
        float val = tile[tx][dy];
        __nv_bfloat16 h = __float2bfloat16(val);
        __nv_bfloat16 l = __float2bfloat16(val - __bfloat162float(h));
        th[(size_t)(bd + dy) * S_LEN + bs + tx] = h;
        tl[(size_t)(bd + dy) * S_LEN + bs + tx] = l;
    }
}

// ---------------------------------------------------------------------------
// Flash attention: delayed-PV pipeline. BQ=64, 128 thr, 1 CTA/SM.
// Q-hi in registers, Q-lo in SMEM; K and V double-buffered.
// Grid (32 qb reversed, 32 h).
// ---------------------------------------------------------------------------
#define QLDT 272
#define VLDT 144
#define SQL  0                       // Q-lo: 64*272 = 17408
#define SK0  17408                   // K buffers: KH +0, KL +17408
#define SK1  52224
#define SV0  87040                   // V buffers: VH +0, VL +18432
#define SV1  123904
#define FLASH_SMEM 160768

__global__ __launch_bounds__(128, 1) void flash_tc(
    const __nv_bfloat16* __restrict__ qh, const __nv_bfloat16* __restrict__ ql,
    const __nv_bfloat16* __restrict__ kh, const __nv_bfloat16* __restrict__ kl,
    const __nv_bfloat16* __restrict__ vth, const __nv_bfloat16* __restrict__ vtl,
    __nv_bfloat16* __restrict__ ohi, __nv_bfloat16* __restrict__ olo) {
    extern __shared__ char sm[];
    const int qb = (int)gridDim.x - 1 - (int)blockIdx.x;
    const int h  = blockIdx.y;
    const int kvh = h >> 2;
    const int tid = threadIdx.x;
    const int lane = tid & 31;
    const int w = tid >> 5;
    const int q0 = qb * 64;
    const float scale = 0.08838834764831845f;
    uint32_t sb = (uint32_t)__cvta_generic_to_shared(sm);

    const int brow = (lane & 7) + ((lane >> 4) << 3);
    const int bch = (lane >> 3) & 1;

    // stage Q-hi (into SV0, temp) and Q-lo (into SQL, persistent)
    for (int i = tid; i < 1024; i += 128) {
        int r = i >> 4;
        int c = i & 15;
        size_t goff = (size_t)(q0 + r) * HID + h * HD + c * 8;
        *(uint4*)(sm + SV0 + r * QLDT + c * 16) = *(const uint4*)(qh + goff);
        *(uint4*)(sm + SQL + r * QLDT + c * 16) = *(const uint4*)(ql + goff);
    }
    __syncthreads();
    uint32_t qf[8][4];
#pragma unroll
    for (int kf = 0; kf < 8; kf++) {
        uint32_t aoff = (uint32_t)((w * 16 + (lane & 15)) * QLDT + kf * 32 + (lane >> 4) * 16);
        ldsm_x4(sb + SV0 + aoff, qf[kf][0], qf[kf][1], qf[kf][2], qf[kf][3]);
    }
    __syncthreads();   // SV0 free

    auto loadK = [&](int kb2) {
        const int k0 = kb2 * 64;
        uint32_t kdst = sb + ((kb2 & 1) ? SK1 : SK0);
#pragma unroll
        for (int i0 = 0; i0 < 16; i0++) {
            int i = tid + i0 * 128;
            int mat = i >> 10;
            int idx = i & 1023;
            int r = idx >> 4;
            int c = idx & 15;
            const void* src = (mat ? kl : kh) + (size_t)(k0 + r) * KVDIM + kvh * HD + c * 8;
            asm volatile("cp.async.cg.shared.global [%0], [%1], 16;"
                         :: "r"(kdst + mat * 17408 + r * QLDT + c * 16), "l"(src));
        }
        asm volatile("cp.async.commit_group;");
    };
    auto loadV = [&](int kb2) {
        const int k0 = kb2 * 64;
        uint32_t vdst = sb + ((kb2 & 1) ? SV1 : SV0);
#pragma unroll
        for (int i0 = 0; i0 < 16; i0++) {
            int i = tid + i0 * 128;
            int mat = i >> 10;
            int idx = i & 1023;
            int r = idx >> 3;
            int c = idx & 7;
            const void* src = (mat ? vtl : vth) + (size_t)(kvh * HD + r) * S_LEN + k0 + c * 8;
            asm volatile("cp.async.cg.shared.global [%0], [%1], 16;"
                         :: "r"(vdst + mat * 18432 + r * VLDT + c * 16), "l"(src));
        }
        asm volatile("cp.async.commit_group;");
    };

    float m0 = -1e30f, m1 = -1e30f, l0 = 0.f, l1 = 0.f;
    float oa[16][4];
#pragma unroll
    for (int i = 0; i < 16; i++)
#pragma unroll
        for (int t = 0; t < 4; t++) oa[i][t] = 0.f;
    uint32_t php[8][2], plp[8][2];

    const int r0g = q0 + w * 16 + (lane >> 2);
    const int r1g = r0g + 8;

    auto do_qk = [&](int kb2, float (*s)[4]) {
        const uint32_t kbase = sb + ((kb2 & 1) ? SK1 : SK0);
#pragma unroll
        for (int kf = 0; kf < 8; kf++) {
            uint32_t aoff = (uint32_t)((w * 16 + (lane & 15)) * QLDT + kf * 32 + (lane >> 4) * 16);
            uint32_t qlf[4];
            ldsm_x4(sb + SQL + aoff, qlf[0], qlf[1], qlf[2], qlf[3]);
#pragma unroll
            for (int np = 0; np < 4; np++) {
                uint32_t boff = (uint32_t)((np * 16 + brow) * QLDT + kf * 32 + bch * 16);
                uint32_t bh[4], bl[4];
                ldsm_x4(kbase + boff, bh[0], bh[1], bh[2], bh[3]);
                ldsm_x4(kbase + 17408 + boff, bl[0], bl[1], bl[2], bl[3]);
                mma_bf16(s[np * 2], qf[kf], bh);
                mma_bf16(s[np * 2], qf[kf], bl);
                mma_bf16(s[np * 2], qlf, bh);
                mma_bf16(s[np * 2 + 1], qf[kf], bh + 2);
                mma_bf16(s[np * 2 + 1], qf[kf], bl + 2);
                mma_bf16(s[np * 2 + 1], qlf, bh + 2);
            }
        }
    };

    auto do_pv = [&](int vsel) {
        uint32_t vbase = sb + (vsel ? SV1 : SV0);
#pragma unroll
        for (int kf2 = 0; kf2 < 4; kf2++) {
            uint32_t pah[4] = {php[2 * kf2][0], php[2 * kf2][1],
                               php[2 * kf2 + 1][0], php[2 * kf2 + 1][1]};
            uint32_t pal[4] = {plp[2 * kf2][0], plp[2 * kf2][1],
                               plp[2 * kf2 + 1][0], plp[2 * kf2 + 1][1]};
#pragma unroll
            for (int np = 0; np < 8; np++) {
                uint32_t voff = (uint32_t)((np * 16 + brow) * VLDT + kf2 * 32 + bch * 16);
                uint32_t vh[4], vl[4];
                ldsm_x4(vbase + voff, vh[0], vh[1], vh[2], vh[3]);
                ldsm_x4(vbase + 18432 + voff, vl[0], vl[1], vl[2], vl[3]);
                mma_bf16(oa[np * 2], pah, vh);
                mma_bf16(oa[np * 2], pah, vl);
                mma_bf16(oa[np * 2], pal, vh);
                mma_bf16(oa[np * 2 + 1], pah, vh + 2);
                mma_bf16(oa[np * 2 + 1], pah, vl + 2);
                mma_bf16(oa[np * 2 + 1], pal, vh + 2);
            }
        }
    };

    loadK(0);                 // G: K0
    loadK(1);                 // G: K1

    // ---------------- peeled iteration kb = 0 (no PV) ----------------
    {
        asm volatile("cp.async.wait_group 1;");    // K0 done
        __syncthreads();
        loadV(0);                                  // G: V0
        float s[8][4];
#pragma unroll
        for (int nf = 0; nf < 8; nf++)
#pragma unroll
            for (int t = 0; t < 4; t++) s[nf][t] = 0.f;
        do_qk(0, s);
        const bool diag = (qb == 0);
#pragma unroll
        for (int nf = 0; nf < 8; nf++) {
            int cg = nf * 8 + (lane & 3) * 2;
            s[nf][0] = (diag && cg > r0g)     ? -1e30f : s[nf][0] * scale;
            s[nf][1] = (diag && cg + 1 > r0g) ? -1e30f : s[nf][1] * scale;
            s[nf][2] = (diag && cg > r1g)     ? -1e30f : s[nf][2] * scale;
            s[nf][3] = (diag && cg + 1 > r1g) ? -1e30f : s[nf][3] * scale;
        }
        __syncthreads();
        if (2 <= qb) loadK(2);
        else         asm volatile("cp.async.commit_group;");

        float mx0 = -1e30f, mx1 = -1e30f;
#pragma unroll
        for (int nf = 0; nf < 8; nf++) {
            mx0 = fmaxf(mx0, fmaxf(s[nf][0], s[nf][1]));
            mx1 = fmaxf(mx1, fmaxf(s[nf][2], s[nf][3]));
        }
        mx0 = fmaxf(mx0, __shfl_xor_sync(0xffffffffu, mx0, 1));
        mx0 = fmaxf(mx0, __shfl_xor_sync(0xffffffffu, mx0, 2));
        mx1 = fmaxf(mx1, __shfl_xor_sync(0xffffffffu, mx1, 1));
        mx1 = fmaxf(mx1, __shfl_xor_sync(0xffffffffu, mx1, 2));
        m0 = mx0; m1 = mx1;
        float rs0 = 0.f, rs1 = 0.f;
#pragma unroll
        for (int nf = 0; nf < 8; nf++) {
            s[nf][0] = __expf(s[nf][0] - m0); rs0 += s[nf][0];
            s[nf][1] = __expf(s[nf][1] - m0); rs0 += s[nf][1];
            s[nf][2] = __expf(s[nf][2] - m1); rs1 += s[nf][2];
            s[nf][3] = __expf(s[nf][3] - m1); rs1 += s[nf][3];
        }
        rs0 += __shfl_xor_sync(0xffffffffu, rs0, 1);
        rs0 += __shfl_xor_sync(0xffffffffu, rs0, 2);
        rs1 += __shfl_xor_sync(0xffffffffu, rs1, 1);
        rs1 += __shfl_xor_sync(0xffffffffu, rs1, 2);
        l0 = rs0; l1 = rs1;
#pragma unroll
        for (int nf = 0; nf < 8; nf++) {
            php[nf][0] = pack_hl(s[nf][0], s[nf][1], plp[nf][0]);
            php[nf][1] = pack_hl(s[nf][2], s[nf][3], plp[nf][1]);
        }
    }

    // ---------------- main loop kb = 1 .. qb (delayed PV) ----------------
    for (int kb = 1; kb <= qb; kb++) {
        const int k0 = kb * 64;
        asm volatile("cp.async.wait_group 1;");    // K(kb), V(kb-1) done
        __syncthreads();
        loadV(kb);

        float s[8][4];
#pragma unroll
        for (int nf = 0; nf < 8; nf++)
#pragma unroll
            for (int t = 0; t < 4; t++) s[nf][t] = 0.f;
        do_qk(kb, s);

        const bool diag = (kb == qb);
#pragma unroll
        for (int nf = 0; nf < 8; nf++) {
            int cg = k0 + nf * 8 + (lane & 3) * 2;
            s[nf][0] = (diag && cg > r0g)     ? -1e30f : s[nf][0] * scale;
            s[nf][1] = (diag && cg + 1 > r0g) ? -1e30f : s[nf][1] * scale;
            s[nf][2] = (diag && cg > r1g)     ? -1e30f : s[nf][2] * scale;
            s[nf][3] = (diag && cg + 1 > r1g) ? -1e30f : s[nf][3] * scale;
        }
        __syncthreads();                           // K(kb) reads complete
        if (kb + 2 <= qb) loadK(kb + 2);
        else              asm volatile("cp.async.commit_group;");

        // ---- softmax(kb) + PV(kb-1) in one scheduling region ----
        float mx0 = -1e30f, mx1 = -1e30f;
#pragma unroll
        for (int nf = 0; nf < 8; nf++) {
            mx0 = fmaxf(mx0, fmaxf(s[nf][0], s[nf][1]));
            mx1 = fmaxf(mx1, fmaxf(s[nf][2], s[nf][3]));
        }
        mx0 = fmaxf(mx0, __shfl_xor_sync(0xffffffffu, mx0, 1));
        mx0 = fmaxf(mx0, __shfl_xor_sync(0xffffffffu, mx0, 2));
        mx1 = fmaxf(mx1, __shfl_xor_sync(0xffffffffu, mx1, 1));
        mx1 = fmaxf(mx1, __shfl_xor_sync(0xffffffffu, mx1, 2));
        float mn0 = fmaxf(m0, mx0);
        float mn1 = fmaxf(m1, mx1);
        float c0 = __expf(m0 - mn0);
        float c1 = __expf(m1 - mn1);
        m0 = mn0; m1 = mn1;
        float rs0 = 0.f, rs1 = 0.f;
#pragma unroll
        for (int nf = 0; nf < 8; nf++) {
            s[nf][0] = __expf(s[nf][0] - m0); rs0 += s[nf][0];
            s[nf][1] = __expf(s[nf][1] - m0); rs0 += s[nf][1];
            s[nf][2] = __expf(s[nf][2] - m1); rs1 += s[nf][2];
            s[nf][3] = __expf(s[nf][3] - m1); rs1 += s[nf][3];
        }
        rs0 += __shfl_xor_sync(0xffffffffu, rs0, 1);
        rs0 += __shfl_xor_sync(0xffffffffu, rs0, 2);
        rs1 += __shfl_xor_sync(0xffffffffu, rs1, 1);
        rs1 += __shfl_xor_sync(0xffffffffu, rs1, 2);

        do_pv((kb - 1) & 1);                       // O += P(kb-1)·V(kb-1)

        l0 = l0 * c0 + rs0;
        l1 = l1 * c1 + rs1;
#pragma unroll
        for (int i = 0; i < 16; i++) {             // rescale AFTER PV(kb-1)
            oa[i][0] *= c0; oa[i][1] *= c0;
            oa[i][2] *= c1; oa[i][3] *= c1;
        }
#pragma unroll
        for (int nf = 0; nf < 8; nf++) {
            php[nf][0] = pack_hl(s[nf][0], s[nf][1], plp[nf][0]);
            php[nf][1] = pack_hl(s[nf][2], s[nf][3], plp[nf][1]);
        }
    }

    // ---------------- final pending PV(qb) ----------------
    asm volatile("cp.async.wait_group 0;");
    __syncthreads();
    do_pv(qb & 1);

    const float inv0 = 1.0f / l0;
    const float inv1 = 1.0f / l1;
#pragma unroll
    for (int nf2 = 0; nf2 < 16; nf2++) {
        int col = h * HD + nf2 * 8 + (lane & 3) * 2;
        uint32_t lo32, hi32;
        hi32 = pack_hl(oa[nf2][0] * inv0, oa[nf2][1] * inv0, lo32);
        *(uint32_t*)&ohi[(size_t)r0g * HID + col] = hi32;
        *(uint32_t*)&olo[(size_t)r0g * HID + col] = lo32;
        hi32 = pack_hl(oa[nf2][2] * inv1, oa[nf2][3] * inv1, lo32);
        *(uint32_t*)&ohi[(size_t)r1g * HID + col] = hi32;
        *(uint32_t*)&olo[(size_t)r1g * HID + col] = lo32;
    }
}

// ---------------------------------------------------------------------------
// launcher
// ---------------------------------------------------------------------------
extern "C" void kernel_launch(void* const* d_in, const int* in_sizes, int n_in,
                              void* d_out, int out_size) {
    const float* hidden = (const float*)d_in[0];
    const float* cosb = (const float*)d_in[2];
    const float* sinb = (const float*)d_in[3];
    const float* wq = (const float*)d_in[4];
    const float* wk = (const float*)d_in[5];
    const float* wv = (const float*)d_in[6];
    const float* wo = (const float*)d_in[7];
    float* out = (float*)d_out;

    float* v;
    cudaGetSymbolAddress((void**)&v, g_v);
    __nv_bfloat16 *at_hi, *at_lo, *qr_hi, *qr_lo, *kr_hi, *kr_lo, *vt_hi, *vt_lo;
    cudaGetSymbolAddress((void**)&at_hi, g_attn_hi);
    cudaGetSymbolAddress((void**)&at_lo, g_attn_lo);
    cudaGetSymbolAddress((void**)&qr_hi, g_qr_hi);
    cudaGetSymbolAddress((void**)&qr_lo, g_qr_lo);
    cudaGetSymbolAddress((void**)&kr_hi, g_kr_hi);
    cudaGetSymbolAddress((void**)&kr_lo, g_kr_lo);
    cudaGetSymbolAddress((void**)&vt_hi, g_vt_hi);
    cudaGetSymbolAddress((void**)&vt_lo, g_vt_lo);

    split_all<<<SPLIT_GRID, 256>>>(hidden, wq, wk, wv, wo);

    cudaFuncSetAttribute(gemm_qkv, cudaFuncAttributeMaxDynamicSharedMemorySize,
                         GEMM_SMEM);
    cudaFuncSetAttribute(gemm_o, cudaFuncAttributeMaxDynamicSharedMemorySize,
                         GEMM_SMEM);

    gemm_qkv<<<dim3(S_LEN / 256, 48), 256, GEMM_SMEM>>>(cosb, sinb);

    transpose_split<<<dim3(S_LEN / 32, KVDIM / 32), dim3(32, 8)>>>(v, vt_hi, vt_lo);

    cudaFuncSetAttribute(flash_tc, cudaFuncAttributeMaxDynamicSharedMemorySize,
                         FLASH_SMEM);
    flash_tc<<<dim3(32, 32), 128, FLASH_SMEM>>>(qr_hi, qr_lo, kr_hi, kr_lo,
                                                vt_hi, vt_lo, at_hi, at_lo);

    gemm_o<<<dim3(S_LEN / 256, HID / 128), 256, GEMM_SMEM>>>(out);
}

// round 10
// speedup vs baseline: 1.0212x; 1.0212x over previous
#include <cuda_runtime.h>
#include <cuda_bf16.h>
#include <stdint.h>

// ---------------------------------------------------------------------------
// LlamaAttention: S=2048, HID=4096, NH=32, NKV=8, D=128
// All matmuls via warp mma.sync bf16x3 (tcgen05 unavailable: PTX target 103).
// RoPE fused into QKV-GEMM epilogue. Flash: BQ=64, Q in registers,
// K double-buffered / V pipelined, 106.5KB SMEM -> 2 CTAs/SM,
// chunk-interleaved P-pack + PV, exp2-domain softmax.
// ---------------------------------------------------------------------------

#define S_LEN 2048
#define HID   4096
#define NH    32
#define NKV   8
#define HD    128
#define KVDIM (NKV * HD)   // 1024

// fp32 scratch (V only)
__device__ float g_v[S_LEN * KVDIM];

// bf16 split scratch
__device__ __nv_bfloat16 g_hid_hi[S_LEN * HID];
__device__ __nv_bfloat16 g_hid_lo[S_LEN * HID];
__device__ __nv_bfloat16 g_wq_hi[HID * HID];
__device__ __nv_bfloat16 g_wq_lo[HID * HID];
__device__ __nv_bfloat16 g_wk_hi[KVDIM * HID];
__device__ __nv_bfloat16 g_wk_lo[KVDIM * HID];
__device__ __nv_bfloat16 g_wv_hi[KVDIM * HID];
__device__ __nv_bfloat16 g_wv_lo[KVDIM * HID];
__device__ __nv_bfloat16 g_wo_hi[HID * HID];
__device__ __nv_bfloat16 g_wo_lo[HID * HID];
__device__ __nv_bfloat16 g_attn_hi[S_LEN * HID];
__device__ __nv_bfloat16 g_attn_lo[S_LEN * HID];
__device__ __nv_bfloat16 g_qr_hi[S_LEN * HID];
__device__ __nv_bfloat16 g_qr_lo[S_LEN * HID];
__device__ __nv_bfloat16 g_kr_hi[S_LEN * KVDIM];
__device__ __nv_bfloat16 g_kr_lo[S_LEN * KVDIM];
__device__ __nv_bfloat16 g_vt_hi[KVDIM * S_LEN];
__device__ __nv_bfloat16 g_vt_lo[KVDIM * S_LEN];

__device__ __forceinline__ uint32_t pack_hl(float f0, float f1, uint32_t& lo) {
    __nv_bfloat162 h = __floats2bfloat162_rn(f0, f1);
    float r0 = f0 - __bfloat162float(h.x);
    float r1 = f1 - __bfloat162float(h.y);
    __nv_bfloat162 l = __floats2bfloat162_rn(r0, r1);
    lo = *(uint32_t*)&l;
    return *(uint32_t*)&h;
}

// ---------------------------------------------------------------------------
// fused split: hidden + wq + wk + wv + wo in ONE launch. 8 elems/thread.
// ---------------------------------------------------------------------------
#define N_HID (S_LEN * HID)
#define N_WQ  (HID * HID)
#define N_WKV (KVDIM * HID)
#define SEG0  N_HID
#define SEG1  (SEG0 + N_WQ)
#define SEG2  (SEG1 + N_WKV)
#define SEG3  (SEG2 + N_WKV)
#define SEG4  (SEG3 + N_WQ)
#define SPLIT_GRID (SEG4 / (8 * 256))

__device__ __forceinline__ void split8(const float* src, __nv_bfloat16* hi,
                                       __nv_bfloat16* lo, int off) {
    float4 f[2];
    f[0] = *(const float4*)(src + off);
    f[1] = *(const float4*)(src + off + 4);
#pragma unroll
    for (int j = 0; j < 2; j++) {
        __nv_bfloat16 h0 = __float2bfloat16(f[j].x);
        __nv_bfloat16 h1 = __float2bfloat16(f[j].y);
        __nv_bfloat16 h2 = __float2bfloat16(f[j].z);
        __nv_bfloat16 h3 = __float2bfloat16(f[j].w);
        __nv_bfloat16 l0 = __float2bfloat16(f[j].x - __bfloat162float(h0));
        __nv_bfloat16 l1 = __float2bfloat16(f[j].y - __bfloat162float(h1));
        __nv_bfloat16 l2 = __float2bfloat16(f[j].z - __bfloat162float(h2));
        __nv_bfloat16 l3 = __float2bfloat16(f[j].w - __bfloat162float(h3));
        ushort4 hv, lv;
        hv.x = *(unsigned short*)&h0; hv.y = *(unsigned short*)&h1;
        hv.z = *(unsigned short*)&h2; hv.w = *(unsigned short*)&h3;
        lv.x = *(unsigned short*)&l0; lv.y = *(unsigned short*)&l1;
        lv.z = *(unsigned short*)&l2; lv.w = *(unsigned short*)&l3;
        *(ushort4*)(hi + off + j * 4) = hv;
        *(ushort4*)(lo + off + j * 4) = lv;
    }
}

__global__ void split_all(const float* __restrict__ hidden,
                          const float* __restrict__ wq,
                          const float* __restrict__ wk,
                          const float* __restrict__ wv,
                          const float* __restrict__ wo) {
    int g = (blockIdx.x * blockDim.x + threadIdx.x) * 8;
    if (g < SEG0)      split8(hidden, g_hid_hi, g_hid_lo, g);
    else if (g < SEG1) split8(wq, g_wq_hi, g_wq_lo, g - SEG0);
    else if (g < SEG2) split8(wk, g_wk_hi, g_wk_lo, g - SEG1);
    else if (g < SEG3) split8(wv, g_wv_hi, g_wv_lo, g - SEG2);
    else               split8(wo, g_wo_hi, g_wo_lo, g - SEG3);
}

// ---------------------------------------------------------------------------
// warp-MMA primitives
// ---------------------------------------------------------------------------
__device__ __forceinline__ void ldsm_x4(uint32_t addr, uint32_t& r0, uint32_t& r1,
                                        uint32_t& r2, uint32_t& r3) {
    asm volatile("ldmatrix.sync.aligned.m8n8.x4.shared.b16 {%0,%1,%2,%3}, [%4];"
                 : "=r"(r0), "=r"(r1), "=r"(r2), "=r"(r3) : "r"(addr));
}

__device__ __forceinline__ void mma_bf16(float* c, const uint32_t* a, const uint32_t* b) {
    asm volatile(
        "mma.sync.aligned.m16n8k16.row.col.f32.bf16.bf16.f32 "
        "{%0,%1,%2,%3},{%4,%5,%6,%7},{%8,%9},{%0,%1,%2,%3};"
        : "+f"(c[0]), "+f"(c[1]), "+f"(c[2]), "+f"(c[3])
        : "r"(a[0]), "r"(a[1]), "r"(a[2]), "r"(a[3]), "r"(b[0]), "r"(b[1]));
}

// ---------------------------------------------------------------------------
// bf16x3 GEMM body: block 256x128, warp 64x64, BK=64, 256 thr, 2-stage.
// Epilogue: 0 = fp32 store, 1 = RoPE + bf16 hi/lo split store.
// ---------------------------------------------------------------------------
#define GBK  64
#define LDT  144
#define A_T  (256 * LDT)
#define B_T  (128 * LDT)
#define STG  (2 * A_T + 2 * B_T)
#define GEMM_SMEM (2 * STG)

__device__ __forceinline__ void gemm_body256(
    const __nv_bfloat16* __restrict__ Ah, const __nv_bfloat16* __restrict__ Al,
    const __nv_bfloat16* __restrict__ Bh, const __nv_bfloat16* __restrict__ Bl,
    float* __restrict__ Cf, __nv_bfloat16* __restrict__ Chi,
    __nv_bfloat16* __restrict__ Clo,
    const float* __restrict__ cosb, const float* __restrict__ sinb,
    int mode, int N, int K, int bm, int bn, char* smem) {
    const int tid = threadIdx.x;
    const int lane = tid & 31;
    const int warp = tid >> 5;
    const int wr = warp >> 1;
    const int wc = warp & 1;
    uint32_t sbase = (uint32_t)__cvta_generic_to_shared(smem);

    float acc[4][8][4];
#pragma unroll
    for (int mi = 0; mi < 4; mi++)
#pragma unroll
        for (int ni = 0; ni < 8; ni++)
#pragma unroll
            for (int t = 0; t < 4; t++) acc[mi][ni][t] = 0.f;

    auto load_stage = [&](int s, int it) {
        const int kbase = it * GBK;
        uint32_t dst0 = sbase + s * STG;
#pragma unroll
        for (int i = 0; i < 24; i++) {
            int c = tid + i * 256;
            const __nv_bfloat16* gsrc;
            uint32_t daddr;
            if (c < 4096) {
                int mat = c >> 11;
                int idx = c & 2047;
                int row = idx >> 3;
                int ch = idx & 7;
                gsrc = (mat ? Al : Ah) + (size_t)(bm + row) * K + kbase + ch * 8;
                daddr = dst0 + mat * A_T + row * LDT + ch * 16;
            } else {
                int cb = c - 4096;
                int mat = cb >> 10;
                int idx = cb & 1023;
                int row = idx >> 3;
                int ch = idx & 7;
                gsrc = (mat ? Bl : Bh) + (size_t)(bn + row) * K + kbase + ch * 8;
                daddr = dst0 + 2 * A_T + mat * B_T + row * LDT + ch * 16;
            }
            asm volatile("cp.async.cg.shared.global [%0], [%1], 16;"
                         :: "r"(daddr), "l"(gsrc));
        }
        asm volatile("cp.async.commit_group;");
    };

    const int NIT = K / GBK;
    load_stage(0, 0);
    load_stage(1, 1);

    const int brow = (lane & 7) + ((lane >> 4) << 3);
    const int bch = (lane >> 3) & 1;

    for (int it = 0; it < NIT; it++) {
        asm volatile("cp.async.wait_group 1;");
        __syncthreads();

        uint32_t sa = sbase + (it & 1) * STG;
#pragma unroll
        for (int ks = 0; ks < 4; ks++) {
            uint32_t ah[4][4], al[4][4];
#pragma unroll
            for (int mi = 0; mi < 4; mi++) {
                uint32_t off = (uint32_t)((wr * 64 + mi * 16 + (lane & 15)) * LDT +
                                          ks * 32 + ((lane >> 4) & 1) * 16);
                ldsm_x4(sa + off, ah[mi][0], ah[mi][1], ah[mi][2], ah[mi][3]);
                ldsm_x4(sa + A_T + off, al[mi][0], al[mi][1], al[mi][2], al[mi][3]);
            }
#pragma unroll
            for (int half = 0; half < 2; half++) {
                uint32_t bh[4][2], bl[4][2];
#pragma unroll
                for (int np = 0; np < 2; np++) {
                    uint32_t off = (uint32_t)((wc * 64 + half * 32 + np * 16 + brow) * LDT +
                                              ks * 32 + bch * 16);
                    uint32_t r0, r1, r2, r3;
                    ldsm_x4(sa + 2 * A_T + off, r0, r1, r2, r3);
                    bh[np * 2][0] = r0; bh[np * 2][1] = r1;
                    bh[np * 2 + 1][0] = r2; bh[np * 2 + 1][1] = r3;
                    ldsm_x4(sa + 2 * A_T + B_T + off, r0, r1, r2, r3);
                    bl[np * 2][0] = r0; bl[np * 2][1] = r1;
                    bl[np * 2 + 1][0] = r2; bl[np * 2 + 1][1] = r3;
                }
#pragma unroll
                for (int mi = 0; mi < 4; mi++)
#pragma unroll
                    for (int nf = 0; nf < 4; nf++) {
                        float* a = acc[mi][half * 4 + nf];
                        mma_bf16(a, ah[mi], bh[nf]);
                        mma_bf16(a, ah[mi], bl[nf]);
                        mma_bf16(a, al[mi], bh[nf]);
                    }
            }
        }
        __syncthreads();
        if (it + 2 < NIT) load_stage(it & 1, it + 2);
        else              asm volatile("cp.async.commit_group;");
    }

    if (mode == 0) {
#pragma unroll
        for (int mi = 0; mi < 4; mi++) {
            const int r0 = bm + wr * 64 + mi * 16 + (lane >> 2);
#pragma unroll
            for (int ni = 0; ni < 8; ni++) {
                const int col = bn + wc * 64 + ni * 8 + (lane & 3) * 2;
                *(float2*)&Cf[(size_t)r0 * N + col] = make_float2(acc[mi][ni][0], acc[mi][ni][1]);
                *(float2*)&Cf[(size_t)(r0 + 8) * N + col] = make_float2(acc[mi][ni][2], acc[mi][ni][3]);
            }
        }
    } else {
#pragma unroll
        for (int mi = 0; mi < 4; mi++) {
            const int r0 = bm + wr * 64 + mi * 16 + (lane >> 2);
            const int r1 = r0 + 8;
#pragma unroll
            for (int ni = 0; ni < 8; ni++) {
                const int col = bn + wc * 64 + ni * 8 + (lane & 3) * 2;
                const int i = (col & 127) >> 1;
                float c0 = cosb[r0 * 64 + i];
                float s0 = sinb[r0 * 64 + i];
                float c1 = cosb[r1 * 64 + i];
                float s1 = sinb[r1 * 64 + i];
                float a0 = acc[mi][ni][0], b0 = acc[mi][ni][1];
                float a1 = acc[mi][ni][2], b1 = acc[mi][ni][3];
                float x0 = a0 * c0 - b0 * s0, y0 = a0 * s0 + b0 * c0;
                float x1 = a1 * c1 - b1 * s1, y1 = a1 * s1 + b1 * c1;
                uint32_t lo32, hi32;
                hi32 = pack_hl(x0, y0, lo32);
                *(uint32_t*)&Chi[(size_t)r0 * N + col] = hi32;
                *(uint32_t*)&Clo[(size_t)r0 * N + col] = lo32;
                hi32 = pack_hl(x1, y1, lo32);
                *(uint32_t*)&Chi[(size_t)r1 * N + col] = hi32;
                *(uint32_t*)&Clo[(size_t)r1 * N + col] = lo32;
            }
        }
    }
}

__global__ __launch_bounds__(256, 1) void gemm_qkv(const float* __restrict__ cosb,
                                                   const float* __restrict__ sinb) {
    extern __shared__ char smem[];
    const int bng = blockIdx.y * 128;
    const int bm = blockIdx.x * 256;
    if (bng < HID) {
        gemm_body256(g_hid_hi, g_hid_lo, g_wq_hi, g_wq_lo, nullptr,
                     g_qr_hi, g_qr_lo, cosb, sinb, 1, HID, HID, bm, bng, smem);
    } else if (bng < HID + KVDIM) {
        gemm_body256(g_hid_hi, g_hid_lo, g_wk_hi, g_wk_lo, nullptr,
                     g_kr_hi, g_kr_lo, cosb, sinb, 1, KVDIM, HID, bm, bng - HID, smem);
    } else {
        gemm_body256(g_hid_hi, g_hid_lo, g_wv_hi, g_wv_lo, g_v,
                     nullptr, nullptr, nullptr, nullptr, 0, KVDIM, HID,
                     bm, bng - HID - KVDIM, smem);
    }
}

__global__ __launch_bounds__(256, 1) void gemm_o(float* __restrict__ out) {
    extern __shared__ char smem[];
    gemm_body256(g_attn_hi, g_attn_lo, g_wo_hi, g_wo_lo, out, nullptr, nullptr,
                 nullptr, nullptr, 0, HID, HID,
                 blockIdx.x * 256, blockIdx.y * 128, smem);
}

// ---------------------------------------------------------------------------
// transpose + split: v[S,1024] fp32 -> vT hi/lo [1024, S]
// ---------------------------------------------------------------------------
__global__ void transpose_split(const float* __restrict__ v,
                                __nv_bfloat16* __restrict__ th,
                                __nv_bfloat16* __restrict__ tl) {
    __shared__ float tile[32][33];
    const int bs = blockIdx.x * 32;
    const int bd = blockIdx.y * 32;
    const int tx = threadIdx.x;
    const int ty = threadIdx.y;
#pragma unroll
    for (int i = 0; i < 4; i++) {
        int sy = ty * 4 + i;
        tile[sy][tx] = v[(size_t)(bs + sy) * KVDIM + bd + tx];
    }
    __syncthreads();
#pragma unroll
    for (int i = 0; i < 4; i++) {
        int dy = ty * 4 + i;
        float val = tile[tx][dy];
        __nv_bfloat16 h = __float2bfloat16(val);
        __nv_bfloat16 l = __float2bfloat16(val - __bfloat162float(h));
        th[(size_t)(bd + dy) * S_LEN + bs + tx] = h;
        tl[(size_t)(bd + dy) * S_LEN + bs + tx] = l;
    }
}

// ---------------------------------------------------------------------------
// Flash attention (bf16x3, warp MMA). BQ=64, 128 threads, Q in registers.
// K double-buffered (prefetch), V pipelined single buffer. 106.5KB -> 2 CTA/SM.
// Chunk-interleaved pack+PV; exp2-domain softmax. Grid (32 qb reversed, 32 h).
// ---------------------------------------------------------------------------
#define QLDT 272
#define VLDT 144
#define FK0  0
#define FK1  34816
#define FV   69632
#define FLASH_SMEM (FV + 36864)   // 106496

__global__ __launch_bounds__(128, 2) void flash_tc(
    const __nv_bfloat16* __restrict__ qh, const __nv_bfloat16* __restrict__ ql,
    const __nv_bfloat16* __restrict__ kh, const __nv_bfloat16* __restrict__ kl,
    const __nv_bfloat16* __restrict__ vth, const __nv_bfloat16* __restrict__ vtl,
    __nv_bfloat16* __restrict__ ohi, __nv_bfloat16* __restrict__ olo) {
    extern __shared__ char sm[];
    const int qb = (int)gridDim.x - 1 - (int)blockIdx.x;
    const int h  = blockIdx.y;
    const int kvh = h >> 2;
    const int tid = threadIdx.x;
    const int lane = tid & 31;
    const int w = tid >> 5;
    const int q0 = qb * 64;
    // scale * log2(e): softmax runs in exp2 domain
    const float scale2 = 0.12751744685137577f;
    uint32_t sb = (uint32_t)__cvta_generic_to_shared(sm);

    const int brow = (lane & 7) + ((lane >> 4) << 3);
    const int bch = (lane >> 3) & 1;

    // --- stage Q (hi/lo) in K1 buffer, then load fragments to registers ---
    for (int i = tid; i < 2048; i += 128) {
        int mat = i >> 10;
        int idx = i & 1023;
        int r = idx >> 4;
        int c = idx & 15;
        const __nv_bfloat16* src = (mat ? ql : qh) + (size_t)(q0 + r) * HID + h * HD + c * 8;
        *(uint4*)(sm + FK1 + mat * 17408 + r * QLDT + c * 16) = *(const uint4*)src;
    }
    __syncthreads();
    uint32_t qfh[8][4], qfl[8][4];
#pragma unroll
    for (int kf = 0; kf < 8; kf++) {
        uint32_t aoff = (uint32_t)((w * 16 + (lane & 15)) * QLDT + kf * 32 + (lane >> 4) * 16);
        ldsm_x4(sb + FK1 + aoff, qfh[kf][0], qfh[kf][1], qfh[kf][2], qfh[kf][3]);
        ldsm_x4(sb + FK1 + 17408 + aoff, qfl[kf][0], qfl[kf][1], qfl[kf][2], qfl[kf][3]);
    }
    __syncthreads();

    auto loadK = [&](int kb) {
        const int k0 = kb * 64;
        uint32_t kdst = sb + ((kb & 1) ? FK1 : FK0);
#pragma unroll
        for (int i0 = 0; i0 < 16; i0++) {
            int i = tid + i0 * 128;
            int mat = i >> 10;
            int idx = i & 1023;
            int r = idx >> 4;
            int c = idx & 15;
            const void* src = (mat ? kl : kh) + (size_t)(k0 + r) * KVDIM + kvh * HD + c * 8;
            asm volatile("cp.async.cg.shared.global [%0], [%1], 16;"
                         :: "r"(kdst + mat * 17408 + r * QLDT + c * 16), "l"(src));
        }
        asm volatile("cp.async.commit_group;");
    };
    auto loadV = [&](int kb) {
        const int k0 = kb * 64;
        uint32_t vdst = sb + FV;
#pragma unroll
        for (int i0 = 0; i0 < 16; i0++) {
            int i = tid + i0 * 128;
            int mat = i >> 10;
            int idx = i & 1023;
            int r = idx >> 3;
            int c = idx & 7;
            const void* src = (mat ? vtl : vth) + (size_t)(kvh * HD + r) * S_LEN + k0 + c * 8;
            asm volatile("cp.async.cg.shared.global [%0], [%1], 16;"
                         :: "r"(vdst + mat * 18432 + r * VLDT + c * 16), "l"(src));
        }
        asm volatile("cp.async.commit_group;");
    };

    float m0 = -1e30f, m1 = -1e30f, l0 = 0.f, l1 = 0.f;
    float oa[16][4];
#pragma unroll
    for (int i = 0; i < 16; i++)
#pragma unroll
        for (int t = 0; t < 4; t++) oa[i][t] = 0.f;

    const int r0g = q0 + w * 16 + (lane >> 2);
    const int r1g = r0g + 8;

    loadK(0);   // pending: {K(kb)}

    for (int kb = 0; kb <= qb; kb++) {
        const int k0 = kb * 64;
        loadV(kb);                                     // +V(kb)
        if (kb < qb) loadK(kb + 1);                    // +K(kb+1)
        else         asm volatile("cp.async.commit_group;");
        asm volatile("cp.async.wait_group 2;");        // K(kb) complete
        __syncthreads();

        const uint32_t kbase = sb + ((kb & 1) ? FK1 : FK0);

        // S = Q K^T (Q fragments register-resident)
        float s[8][4];
#pragma unroll
        for (int nf = 0; nf < 8; nf++)
#pragma unroll
            for (int t = 0; t < 4; t++) s[nf][t] = 0.f;

#pragma unroll
        for (int kf = 0; kf < 8; kf++) {
#pragma unroll
            for (int np = 0; np < 4; np++) {
                uint32_t boff = (uint32_t)((np * 16 + brow) * QLDT + kf * 32 + bch * 16);
                uint32_t bh[4], bl[4];
                ldsm_x4(kbase + boff, bh[0], bh[1], bh[2], bh[3]);
                ldsm_x4(kbase + 17408 + boff, bl[0], bl[1], bl[2], bl[3]);
                mma_bf16(s[np * 2], qfh[kf], bh);
                mma_bf16(s[np * 2], qfh[kf], bl);
                mma_bf16(s[np * 2], qfl[kf], bh);
                mma_bf16(s[np * 2 + 1], qfh[kf], bh + 2);
                mma_bf16(s[np * 2 + 1], qfh[kf], bl + 2);
                mma_bf16(s[np * 2 + 1], qfl[kf], bh + 2);
            }
        }

#pragma unroll
        for (int nf = 0; nf < 8; nf++)
#pragma unroll
            for (int t = 0; t < 4; t++) s[nf][t] *= scale2;
        if (kb == qb) {
#pragma unroll
            for (int nf = 0; nf < 8; nf++) {
                int cg = k0 + nf * 8 + (lane & 3) * 2;
                if (cg > r0g)     s[nf][0] = -1e30f;
                if (cg + 1 > r0g) s[nf][1] = -1e30f;
                if (cg > r1g)     s[nf][2] = -1e30f;
                if (cg + 1 > r1g) s[nf][3] = -1e30f;
            }
        }

        // online softmax (exp2 domain)
        float mx0 = -1e30f, mx1 = -1e30f;
#pragma unroll
        for (int nf = 0; nf < 8; nf++) {
            mx0 = fmaxf(mx0, fmaxf(s[nf][0], s[nf][1]));
            mx1 = fmaxf(mx1, fmaxf(s[nf][2], s[nf][3]));
        }
        mx0 = fmaxf(mx0, __shfl_xor_sync(0xffffffffu, mx0, 1));
        mx0 = fmaxf(mx0, __shfl_xor_sync(0xffffffffu, mx0, 2));
        mx1 = fmaxf(mx1, __shfl_xor_sync(0xffffffffu, mx1, 1));
        mx1 = fmaxf(mx1, __shfl_xor_sync(0xffffffffu, mx1, 2));
        float mn0 = fmaxf(m0, mx0);
        float mn1 = fmaxf(m1, mx1);
        float c0 = exp2f(m0 - mn0);
        float c1 = exp2f(m1 - mn1);
        m0 = mn0; m1 = mn1;
        float rs0 = 0.f, rs1 = 0.f;
#pragma unroll
        for (int nf = 0; nf < 8; nf++) {
            s[nf][0] = exp2f(s[nf][0] - m0); rs0 += s[nf][0];
            s[nf][1] = exp2f(s[nf][1] - m0); rs0 += s[nf][1];
            s[nf][2] = exp2f(s[nf][2] - m1); rs1 += s[nf][2];
            s[nf][3] = exp2f(s[nf][3] - m1); rs1 += s[nf][3];
        }
        rs0 += __shfl_xor_sync(0xffffffffu, rs0, 1);
        rs0 += __shfl_xor_sync(0xffffffffu, rs0, 2);
        rs1 += __shfl_xor_sync(0xffffffffu, rs1, 1);
        rs1 += __shfl_xor_sync(0xffffffffu, rs1, 2);
        l0 = l0 * c0 + rs0;
        l1 = l1 * c1 + rs1;
#pragma unroll
        for (int i = 0; i < 16; i++) {
            oa[i][0] *= c0; oa[i][1] *= c0;
            oa[i][2] *= c1; oa[i][3] *= c1;
        }

        asm volatile("cp.async.wait_group 1;");        // V(kb) complete
        __syncthreads();

        // O += P V : chunk-interleaved pack + MMA (small live P window)
#pragma unroll
        for (int kf2 = 0; kf2 < 4; kf2++) {
            uint32_t pah[4], pal[4];
            pah[0] = pack_hl(s[2 * kf2][0], s[2 * kf2][1], pal[0]);
            pah[1] = pack_hl(s[2 * kf2][2], s[2 * kf2][3], pal[1]);
            pah[2] = pack_hl(s[2 * kf2 + 1][0], s[2 * kf2 + 1][1], pal[2]);
            pah[3] = pack_hl(s[2 * kf2 + 1][2], s[2 * kf2 + 1][3], pal[3]);
#pragma unroll
            for (int np = 0; np < 8; np++) {
                uint32_t voff = (uint32_t)((np * 16 + brow) * VLDT + kf2 * 32 + bch * 16);
                uint32_t vh[4], vl[4];
                ldsm_x4(sb + FV + voff, vh[0], vh[1], vh[2], vh[3]);
                ldsm_x4(sb + FV + 18432 + voff, vl[0], vl[1], vl[2], vl[3]);
                mma_bf16(oa[np * 2], pah, vh);
                mma_bf16(oa[np * 2], pah, vl);
                mma_bf16(oa[np * 2], pal, vh);
                mma_bf16(oa[np * 2 + 1], pah, vh + 2);
                mma_bf16(oa[np * 2 + 1], pah, vl + 2);
                mma_bf16(oa[np * 2 + 1], pal, vh + 2);
            }
        }
        __syncthreads();   // V reads done before next iter's loadV
    }

    const float inv0 = 1.0f / l0;
    const float inv1 = 1.0f / l1;
#pragma unroll
    for (int nf2 = 0; nf2 < 16; nf2++) {
        int col = h * HD + nf2 * 8 + (lane & 3) * 2;
        uint32_t lo32, hi32;
        hi32 = pack_hl(oa[nf2][0] * inv0, oa[nf2][1] * inv0, lo32);
        *(uint32_t*)&ohi[(size_t)r0g * HID + col] = hi32;
        *(uint32_t*)&olo[(size_t)r0g * HID + col] = lo32;
        hi32 = pack_hl(oa[nf2][2] * inv1, oa[nf2][3] * inv1, lo32);
        *(uint32_t*)&ohi[(size_t)r1g * HID + col] = hi32;
        *(uint32_t*)&olo[(size_t)r1g * HID + col] = lo32;
    }
}

// ---------------------------------------------------------------------------
// launcher
// ---------------------------------------------------------------------------
extern "C" void kernel_launch(void* const* d_in, const int* in_sizes, int n_in,
                              void* d_out, int out_size) {
    const float* hidden = (const float*)d_in[0];
    const float* cosb = (const float*)d_in[2];
    const float* sinb = (const float*)d_in[3];
    const float* wq = (const float*)d_in[4];
    const float* wk = (const float*)d_in[5];
    const float* wv = (const float*)d_in[6];
    const float* wo = (const float*)d_in[7];
    float* out = (float*)d_out;

    float* v;
    cudaGetSymbolAddress((void**)&v, g_v);
    __nv_bfloat16 *at_hi, *at_lo, *qr_hi, *qr_lo, *kr_hi, *kr_lo, *vt_hi, *vt_lo;
    cudaGetSymbolAddress((void**)&at_hi, g_attn_hi);
    cudaGetSymbolAddress((void**)&at_lo, g_attn_lo);
    cudaGetSymbolAddress((void**)&qr_hi, g_qr_hi);
    cudaGetSymbolAddress((void**)&qr_lo, g_qr_lo);
    cudaGetSymbolAddress((void**)&kr_hi, g_kr_hi);
    cudaGetSymbolAddress((void**)&kr_lo, g_kr_lo);
    cudaGetSymbolAddress((void**)&vt_hi, g_vt_hi);
    cudaGetSymbolAddress((void**)&vt_lo, g_vt_lo);

    split_all<<<SPLIT_GRID, 256>>>(hidden, wq, wk, wv, wo);

    cudaFuncSetAttribute(gemm_qkv, cudaFuncAttributeMaxDynamicSharedMemorySize,
                         GEMM_SMEM);
    cudaFuncSetAttribute(gemm_o, cudaFuncAttributeMaxDynamicSharedMemorySize,
                         GEMM_SMEM);

    gemm_qkv<<<dim3(S_LEN / 256, 48), 256, GEMM_SMEM>>>(cosb, sinb);

    transpose_split<<<dim3(S_LEN / 32, KVDIM / 32), dim3(32, 8)>>>(v, vt_hi, vt_lo);

    cudaFuncSetAttribute(flash_tc, cudaFuncAttributeMaxDynamicSharedMemorySize,
                         FLASH_SMEM);
    flash_tc<<<dim3(32, 32), 128, FLASH_SMEM>>>(qr_hi, qr_lo, kr_hi, kr_lo,
                                                vt_hi, vt_lo, at_hi, at_lo);

    gemm_o<<<dim3(S_LEN / 256, HID / 128), 256, GEMM_SMEM>>>(out);
}